// round 8
// baseline (speedup 1.0000x reference)
#include <cuda_runtime.h>
#include <cstdint>

#define NB 4096
#define NT 32               // 32x32 grid of 128x128 tiles
#define NITEMS 1056         // two 128x64 half-tiles per upper-triangle tile

// quantization scales: products matched exactly: SX*SIV == SMW*SMW (by construction)
#define SX  68.0f
#define SIV 63.0f
#define SMW 65.45227f        // sqrt(68*63) = sqrt(4284)
#define KDQ (0.125f / 4284.0f)

// ---------------- device scratch (static: no allocation allowed) ----------------
// C row (256 int8): [qx | q(-2m) | q(1/v) | q(m/v)], x = v + m^2
// "D" row = C rotated by 128 bytes (16B chunk c -> (c+8)&15), derived at staging.
__device__ int8_t g_C[(size_t)NB * 256];
__device__ float  g_A8[NB];    // 0.125*a_i - 8
__device__ float  g_P8[NB];    // 0.125*p_i
__device__ float  g_Q[NB];     // 1/(p_i + 1e-8)
__device__ double g_pos, g_neg;
// persistent-kernel coordination (self-resetting across graph replays)
__device__ unsigned g_arrive = 0, g_done = 0, g_ticket = 0;
__device__ volatile unsigned g_release = 0;

static __device__ __forceinline__ uint32_t smem_u32(const void* p) {
    uint32_t a;
    asm("{ .reg .u64 t; cvta.to.shared.u64 t, %1; cvt.u32.u64 %0, t; }" : "=r"(a) : "l"(p));
    return a;
}
static __device__ __forceinline__ float frcp(float x) {
    float r; asm("rcp.approx.f32 %0, %1;" : "=f"(r) : "f"(x)); return r;
}
static __device__ __forceinline__ float ftanh(float x) {
    float r; asm("tanh.approx.f32 %0, %1;" : "=f"(r) : "f"(x)); return r;
}
static __device__ __forceinline__ void cpa16(uint32_t dst, const void* src) {
    asm volatile("cp.async.ca.shared.global [%0], [%1], 16;" :: "r"(dst), "l"(src));
}
static __device__ __forceinline__ int q8(float v, float s) {
    float t = fmaxf(fminf(v * s, 127.0f), -127.0f);
    return __float2int_rn(t);
}

// smem: A tile 128x256B (32KB), B tile 64x256B (16KB), params, scratch.
// XOR swizzle on 16B chunks: chunk c at row r lands at (c ^ (r&7)) -> conflict-free
// for both cp.async staging and ldmatrix (8 rows x same logical chunk hit 8 banksets).
#define CS_OFF 0
#define DS_OFF 32768
#define PAR_OFF 49152
#define RED_OFF 52224
#define SMEM_BYTES 52288

// ---- one k32 step of the 128x64 int8 GEMM (warp tile 64x32) ----
static __device__ __forceinline__ void gemm_all(
    uint32_t csA, uint32_t csB, int lane, int warp_m, int warp_n,
    int (&acc)[4][4][4])
{
    #pragma unroll
    for (int s = 0; s < 8; s++) {
        uint32_t af[4][4];
        #pragma unroll
        for (int mi = 0; mi < 4; mi++) {
            int r = warp_m * 64 + mi * 16 + (lane & 15);
            int c16 = 2 * s + (lane >> 4);
            uint32_t addr = csA + r * 256 + ((c16 ^ (r & 7)) << 4);
            asm volatile("ldmatrix.sync.aligned.m8n8.x4.shared.b16 {%0,%1,%2,%3}, [%4];"
                         : "=r"(af[mi][0]), "=r"(af[mi][1]), "=r"(af[mi][2]), "=r"(af[mi][3])
                         : "r"(addr));
        }
        #pragma unroll
        for (int ni = 0; ni < 4; ni++) {
            int r = warp_n * 32 + ni * 8 + (lane & 7);
            int c16 = 2 * s + ((lane >> 3) & 1);
            uint32_t addr = csB + r * 256 + ((c16 ^ (r & 7)) << 4);
            uint32_t b0, b1;
            asm volatile("ldmatrix.sync.aligned.m8n8.x2.shared.b16 {%0,%1}, [%2];"
                         : "=r"(b0), "=r"(b1) : "r"(addr));
            #pragma unroll
            for (int mi = 0; mi < 4; mi++) {
                asm volatile(
                    "mma.sync.aligned.m16n8k32.row.col.s32.s8.s8.s32 "
                    "{%0,%1,%2,%3}, {%4,%5,%6,%7}, {%8,%9}, {%0,%1,%2,%3};"
                    : "+r"(acc[mi][ni][0]), "+r"(acc[mi][ni][1]),
                      "+r"(acc[mi][ni][2]), "+r"(acc[mi][ni][3])
                    : "r"(af[mi][0]), "r"(af[mi][1]), "r"(af[mi][2]), "r"(af[mi][3]),
                      "r"(b0), "r"(b1));
            }
        }
    }
}

static __device__ __forceinline__ void decode_item(unsigned t, int& I, int& J, int& half) {
    int ft = (int)(t >> 1); half = (int)(t & 1); I = 0;
    while (ft >= NT - I) { ft -= NT - I; I++; }
    J = I + ft;
}

__global__ void __launch_bounds__(128, 4) mega_kernel(
    const float* __restrict__ mu, const float* __restrict__ var,
    const int* __restrict__ labels, float* __restrict__ out)
{
    extern __shared__ char smem[];
    uint32_t sbase = smem_u32(smem);
    int tid = threadIdx.x, lane = tid & 31, wid = tid >> 5;

    // ================= phase 0: prep (8 rows per CTA pass, 16 lanes/row) =================
    for (int row0 = blockIdx.x * 8; row0 < NB; row0 += gridDim.x * 8) {
        int row = row0 + (tid >> 4), l16 = tid & 15;   // dims [l16*4, l16*4+4)
        float4 m4 = ((const float4*)(mu  + (size_t)row * 64))[l16];
        float4 v4 = ((const float4*)(var + (size_t)row * 64))[l16];
        float m[4] = {m4.x, m4.y, m4.z, m4.w};
        float v[4] = {v4.x, v4.y, v4.z, v4.w};
        float x[4], n2m[4], iv[4], w[4];
        float pv = 1.0f, av = 0.0f;
        #pragma unroll
        for (int d = 0; d < 4; d++) {
            iv[d]  = frcp(v[d]);
            x[d]   = v[d] + m[d] * m[d];
            n2m[d] = -2.0f * m[d];
            w[d]   = m[d] * iv[d];
            pv *= v[d];
            av = fmaf(m[d] * m[d], iv[d], av);
        }
        // quantize & pack 4 int8 per block
        uint32_t pk[4];
        #pragma unroll
        for (int b = 0; b < 4; b++) {
            const float* s = (b == 0) ? x : (b == 1) ? n2m : (b == 2) ? iv : w;
            float sc = (b == 0) ? SX : (b == 2) ? SIV : SMW;
            int q0 = q8(s[0], sc), q1 = q8(s[1], sc), q2 = q8(s[2], sc), q3 = q8(s[3], sc);
            pk[b] = (uint32_t)(q0 & 255) | ((uint32_t)(q1 & 255) << 8) |
                    ((uint32_t)(q2 & 255) << 16) | ((uint32_t)(q3 & 255) << 24);
        }
        uint32_t* crow = (uint32_t*)(g_C + (size_t)row * 256);
        crow[0 * 16 + l16] = pk[0];
        crow[1 * 16 + l16] = pk[1];
        crow[2 * 16 + l16] = pk[2];
        crow[3 * 16 + l16] = pk[3];

        #pragma unroll
        for (int off = 1; off < 16; off <<= 1) {
            pv *= __shfl_xor_sync(0xffffffffu, pv, off);
            av += __shfl_xor_sync(0xffffffffu, av, off);
        }
        if (l16 == 0) {
            g_A8[row] = 0.125f * av - 8.0f;
            g_P8[row] = 0.125f * pv;
            g_Q[row]  = frcp(pv + 1e-8f);
        }
    }

    // ================= device-wide barrier (all CTAs resident by construction) =================
    __syncthreads();
    if (tid == 0) {
        unsigned target = g_release + 1;
        __threadfence();
        unsigned a = atomicAdd(&g_arrive, 1);
        if (a == gridDim.x - 1) {
            g_arrive = 0;
            g_pos = 0.0; g_neg = 0.0;
            g_ticket = gridDim.x;
            __threadfence();
            atomicAdd((unsigned*)&g_release, 1);
        } else {
            while (g_release < target) __nanosleep(64);
        }
        __threadfence();
    }
    __syncthreads();

    // ================= phase 1: half-tile (128x64) work loop =================
    float* spAI = (float*)(smem + PAR_OFF);
    float* spPI = spAI + 128;
    float* spQI = spPI + 128;
    int*   spLI = (int*)(spQI + 128);
    float* spAJ = (float*)(spLI + 128);     // 64 entries
    float* spPJ = spAJ + 64;
    float* spQJ = spPJ + 64;
    int*   spLJ = (int*)(spQJ + 64);
    float* red  = (float*)(smem + RED_OFF);
    unsigned* tick_s = (unsigned*)(red + 8);

    uint32_t csA = sbase + CS_OFF, csB = sbase + DS_OFF;
    int warp_m = wid & 1, warp_n = wid >> 1;
    float pos = 0.0f, neg = 0.0f;
    unsigned t = blockIdx.x;

    while (t < NITEMS) {
        int I, J, half;
        decode_item(t, I, J, half);
        int Ibase = I * 128, Jbase = J * 128 + half * 64;
        const char* baseI = (const char*)g_C + (size_t)Ibase * 256;
        const char* baseJ = (const char*)g_C + (size_t)Jbase * 256;

        __syncthreads();   // previous item's epilogue done with smem

        if (tid == 0) *tick_s = atomicAdd(&g_ticket, 1);   // next ticket, early

        // stage full item: A 128 rows, B 64 rows (rotated by 8 chunks)
        {
            int row0 = tid >> 4, c16 = tid & 15;
            #pragma unroll
            for (int p = 0; p < 16; p++) {
                int r = row0 + p * 8;
                uint32_t dst = sbase + CS_OFF + r * 256 + ((c16 ^ (r & 7)) << 4);
                cpa16(dst, baseI + r * 256 + c16 * 16);
            }
            #pragma unroll
            for (int p = 0; p < 8; p++) {
                int r = row0 + p * 8;
                uint32_t dst = sbase + DS_OFF + r * 256 + ((c16 ^ (r & 7)) << 4);
                cpa16(dst, baseJ + r * 256 + (((c16 + 8) & 15) << 4));
            }
            asm volatile("cp.async.commit_group;" ::: "memory");
        }
        // params via regular loads (overlap the cp.async)
        spAI[tid] = g_A8[Ibase + tid];
        spPI[tid] = g_P8[Ibase + tid];
        spQI[tid] = g_Q[Ibase + tid];
        spLI[tid] = labels[Ibase + tid];
        if (tid < 64) {
            spAJ[tid] = g_A8[Jbase + tid];
            spPJ[tid] = g_P8[Jbase + tid];
            spQJ[tid] = g_Q[Jbase + tid];
            spLJ[tid] = labels[Jbase + tid];
        }
        asm volatile("cp.async.wait_group 0;" ::: "memory");
        __syncthreads();

        int acc[4][4][4];
        #pragma unroll
        for (int mi = 0; mi < 4; mi++)
            #pragma unroll
            for (int ni = 0; ni < 4; ni++)
                #pragma unroll
                for (int e = 0; e < 4; e++) acc[mi][ni][e] = 0;

        gemm_all(csA, csB, lane, warp_m, warp_n, acc);

        unsigned nt = *tick_s;   // written before the post-stage sync

        // fused epilogue: sym/2 = KDQ*accsum + A8_i + A8_j + P8_i*Q_j + P8_j*Q_i
        // sigmoid(sym) = 0.5 + 0.5*tanh(sym/2)
        const bool diag = (I == J);
        #pragma unroll
        for (int mi = 0; mi < 4; mi++) {
            #pragma unroll
            for (int k = 0; k < 2; k++) {
                int r = warp_m * 64 + mi * 16 + (lane >> 2) + k * 8;
                float RA = spAI[r], RP = spPI[r], RQ = spQI[r];
                int   RL = spLI[r];
                #pragma unroll
                for (int ni = 0; ni < 4; ni++) {
                    int c0 = warp_n * 32 + ni * 8 + (lane & 3) * 2;
                    #pragma unroll
                    for (int e = 0; e < 2; e++) {
                        int c = c0 + e;
                        float vv = (float)acc[mi][ni][k * 2 + e];
                        float s = fmaf(vv, KDQ, RA);
                        s += spAJ[c];
                        s = fmaf(RP, spQJ[c], s);
                        s = fmaf(spPJ[c], RQ, s);
                        float sg = fmaf(ftanh(s), 0.5f, 0.5f);
                        bool count = (!diag) || (half * 64 + c > r);
                        bool same  = (RL == spLJ[c]);
                        if (count) {
                            pos += same ? sg : 0.0f;
                            neg += same ? 0.0f : sg;
                        }
                    }
                }
            }
        }

        t = nt;
    }

    // ================= final reduce + output by last CTA =================
    #pragma unroll
    for (int off = 16; off; off >>= 1) {
        pos += __shfl_xor_sync(0xffffffffu, pos, off);
        neg += __shfl_xor_sync(0xffffffffu, neg, off);
    }
    __syncthreads();
    if (lane == 0) { red[wid] = pos; red[4 + wid] = neg; }
    __syncthreads();
    if (tid == 0) {
        double P = 0.0, Nn = 0.0;
        #pragma unroll
        for (int w = 0; w < 4; w++) { P += (double)red[w]; Nn += (double)red[4 + w]; }
        atomicAdd(&g_pos, P);
        atomicAdd(&g_neg, Nn);
        __threadfence();
        unsigned d = atomicAdd(&g_done, 1);
        if (d == gridDim.x - 1) {
            double TP = 2.0 * atomicAdd(&g_pos, 0.0);
            double TN = 2.0 * atomicAdd(&g_neg, 0.0);
            const double inv = 1.0 / ((double)NB * (double)NB);
            out[0] = (float)(TP * inv);
            out[1] = (float)(TN * inv);
            out[2] = (float)TP;
            out[3] = (float)TN;
            g_done = 0;
        }
    }
}

// ---------------- launcher ----------------
extern "C" void kernel_launch(void* const* d_in, const int* in_sizes, int n_in,
                              void* d_out, int out_size) {
    (void)in_sizes; (void)n_in; (void)out_size;
    const float* mu     = (const float*)d_in[0];
    const float* var    = (const float*)d_in[1];
    const int*   labels = (const int*)d_in[2];
    float* out = (float*)d_out;

    cudaFuncSetAttribute(mega_kernel, cudaFuncAttributeMaxDynamicSharedMemorySize,
                         SMEM_BYTES);
    int occ = 0, sms = 0, dev = 0;
    cudaGetDevice(&dev);
    cudaOccupancyMaxActiveBlocksPerMultiprocessor(&occ, mega_kernel, 128, SMEM_BYTES);
    cudaDeviceGetAttribute(&sms, cudaDevAttrMultiProcessorCount, dev);
    int grid = occ * sms;
    if (grid > NITEMS) grid = NITEMS;
    if (grid < 1) grid = 1;

    mega_kernel<<<grid, 128, SMEM_BYTES>>>(mu, var, labels, out);
}